// round 17
// baseline (speedup 1.0000x reference)
#include <cuda_runtime.h>

// out[b,d,t] = T*x[b,d,t] - 2 * sum_{s ≡ t (mod 2)} x[b,d,s],  T = 1024.
// (Dirichlet-kernel collapse of the rfft -> cos/sin GEMM reference; see R1.)
//
// R14: R13 structure (warp-per-row, register-resident, 256-bit ld/st) with
// PLAIN default-policy stores instead of .cs. The 10.72us six-way plateau is
// explained by the DRAM write-drain ceiling (32MB/replay / 10.72us = 3.0TB/s):
// .cs evict-first *guarantees* every output line drains to DRAM each replay.
// Default policy lets the 32MB dirty output set be rewritten in place in the
// 126MB L2 (input 32MB clean + output 32MB dirty both fit), potentially
// eliminating steady-state DRAM writes. This is the last untested cell of the
// policy/structure matrix (R7's .cs-vs-plain comparison was confounded by
// regs/occupancy). If neutral: 10.72us is the hardware floor; finalize.

#define ROW_LEN        1024
#define THREADS        256          // 8 warps -> 8 rows per block
#define V256_PER_LANE  4            // 4 x 256-bit = 32 floats per lane

struct V8 { unsigned long long a, b, c, d; };   // 8 packed floats

__device__ __forceinline__ V8 ld256(const void* p) {
    V8 v;
    asm volatile("ld.global.nc.v4.b64 {%0,%1,%2,%3}, [%4];"
                 : "=l"(v.a), "=l"(v.b), "=l"(v.c), "=l"(v.d) : "l"(p));
    return v;
}

__device__ __forceinline__ void st256(void* p, const V8& v) {
    asm volatile("st.global.v4.b64 [%0], {%1,%2,%3,%4};"
                 :: "l"(p), "l"(v.a), "l"(v.b), "l"(v.c), "l"(v.d) : "memory");
}

// lo half of each b64 = even element, hi half = odd element.
__device__ __forceinline__ void accum_pair(unsigned long long w,
                                           float& e, float& o) {
    e += __uint_as_float((unsigned)w);
    o += __uint_as_float((unsigned)(w >> 32));
}

__device__ __forceinline__ unsigned long long fma_pair(unsigned long long w,
                                                       float T, float E2,
                                                       float O2) {
    float lo = fmaf(T, __uint_as_float((unsigned)w),         -E2);
    float hi = fmaf(T, __uint_as_float((unsigned)(w >> 32)), -O2);
    return (unsigned long long)__float_as_uint(lo)
         | ((unsigned long long)__float_as_uint(hi) << 32);
}

__global__ __launch_bounds__(THREADS)
void season_block_46428596469890_kernel(const float* __restrict__ x,
                                        float* __restrict__ out) {
    const int lane = threadIdx.x & 31;
    const int warp = threadIdx.x >> 5;
    const long long row = (long long)blockIdx.x * 8 + warp;

    const char* xr = reinterpret_cast<const char*>(x) + row * (ROW_LEN * 4);
    char* outr     = reinterpret_cast<char*>(out)     + row * (ROW_LEN * 4);

    // Front-batched 256-bit loads: 4 per lane, 32B each.
    V8 v[V256_PER_LANE];
    #pragma unroll
    for (int j = 0; j < V256_PER_LANE; j++)
        v[j] = ld256(xr + ((size_t)(j * 32 + lane) << 5));

    // Even elements in lo halves, odd in hi halves (element base = mult of 8).
    float esum = 0.0f, osum = 0.0f;
    #pragma unroll
    for (int j = 0; j < V256_PER_LANE; j++) {
        accum_pair(v[j].a, esum, osum);
        accum_pair(v[j].b, esum, osum);
        accum_pair(v[j].c, esum, osum);
        accum_pair(v[j].d, esum, osum);
    }

    // Warp-only reduction; every lane ends with the full-row sums.
    #pragma unroll
    for (int off = 16; off > 0; off >>= 1) {
        esum += __shfl_xor_sync(0xffffffffu, esum, off);
        osum += __shfl_xor_sync(0xffffffffu, osum, off);
    }

    const float E2 = 2.0f * esum;
    const float O2 = 2.0f * osum;
    const float T  = (float)ROW_LEN;

    #pragma unroll
    for (int j = 0; j < V256_PER_LANE; j++) {
        V8 r;
        r.a = fma_pair(v[j].a, T, E2, O2);
        r.b = fma_pair(v[j].b, T, E2, O2);
        r.c = fma_pair(v[j].c, T, E2, O2);
        r.d = fma_pair(v[j].d, T, E2, O2);
        st256(outr + ((size_t)(j * 32 + lane) << 5), r);
    }
}

extern "C" void kernel_launch(void* const* d_in, const int* in_sizes, int n_in,
                              void* d_out, int out_size) {
    const float* x = (const float*)d_in[0];
    float* out = (float*)d_out;
    const int n_rows = in_sizes[0] / ROW_LEN;       // 8192
    season_block_46428596469890_kernel<<<n_rows / 8, THREADS>>>(x, out);
}